// round 1
// baseline (speedup 1.0000x reference)
#include <cuda_runtime.h>
#include <math.h>

#define BB 4
#define CC 512
#define HW 1024
#define KK 64

// ---------------- scratch (no allocations allowed) ----------------
__device__ float g_w1[KK*CC];          // inv2
__device__ float g_w2[KK*CC];          // anchor*inv2
__device__ float g_inv[KK*CC];         // inv
__device__ float g_ck[KK];             // sum_c anchor^2*inv2
__device__ float g_d2p[2][BB*KK*HW];   // partial d2 (C split)
__device__ float g_nump[4][BB*KK*CC];  // partial aggregation (n split)
__device__ float g_rowsq[BB*KK];       // post-rownorm sumsq per (b,k)

// ---------------- K1: weights prep ----------------
__global__ void k1_prep(const float* __restrict__ anchor,
                        const float* __restrict__ sigma) {
    int k = blockIdx.x;
    int tid = threadIdx.x;
    __shared__ float red[256];
    float ck = 0.f;
    for (int c = tid; c < CC; c += 256) {
        int idx = k*CC + c;
        float s  = 1.f / (1.f + expf(-sigma[idx]));
        float iv = 1.f / (s + 1e-7f);
        float i2 = iv * iv;
        float a  = anchor[idx];
        g_w1[idx]  = i2;
        g_w2[idx]  = a * i2;
        g_inv[idx] = iv;
        ck += a * a * i2;
    }
    red[tid] = ck; __syncthreads();
    for (int s = 128; s > 0; s >>= 1) {
        if (tid < s) red[tid] += red[tid + s];
        __syncthreads();
    }
    if (tid == 0) g_ck[k] = red[0];
}

// ---------------- K2: distance GEMM ----------------
// grid 256 blocks x 128 threads. Block: 32 k x 64 n, C-range 256 (split 2).
__global__ void k2_dist(const float* __restrict__ x) {
    int bid = blockIdx.x;
    int cs = bid & 1;
    int kt = (bid >> 1) & 1;
    int nt = (bid >> 2) & 15;
    int b  = bid >> 6;
    int k0 = kt * 32, n0 = nt * 64, c0 = cs * 256;

    __shared__ float xs[32][64];
    __shared__ float w1t[32][36];   // [c][k], padded
    __shared__ float w2t[32][36];

    int tid = threadIdx.x;
    int kr = tid >> 4;     // 0..7  -> k = k0 + kr*4 + i
    int nr = tid & 15;     // 0..15 -> n = n0 + nr*4 + j

    float acc[4][4];
#pragma unroll
    for (int i = 0; i < 4; i++)
#pragma unroll
        for (int j = 0; j < 4; j++) acc[i][j] = 0.f;

    for (int cc = 0; cc < 256; cc += 32) {
        __syncthreads();
        // x chunk: 32 c-rows x 64 n (coalesced float4)
#pragma unroll
        for (int l = 0; l < 4; l++) {
            int idx = tid + l * 128;          // 0..511 float4 slots
            int row = idx >> 4;
            int col = (idx & 15) << 2;
            float4 v = *(const float4*)&x[(b*CC + c0 + cc + row)*HW + n0 + col];
            *(float4*)&xs[row][col] = v;
        }
        // weights transposed into [c][k]
#pragma unroll
        for (int l = 0; l < 8; l++) {
            int idx = tid + l * 256;          // wrong stride guard below
            (void)idx;
        }
#pragma unroll
        for (int l = 0; l < 8; l++) {
            int idx = tid + l * 128;          // 0..1023
            int kk  = idx >> 5;               // 0..31
            int ccc = idx & 31;
            int g   = (k0 + kk)*CC + c0 + cc + ccc;
            w1t[ccc][kk] = g_w1[g];
            w2t[ccc][kk] = g_w2[g];
        }
        __syncthreads();
#pragma unroll
        for (int c = 0; c < 32; c++) {
            float4 xv = *(const float4*)&xs[c][nr << 2];
            float4 wa = *(const float4*)&w1t[c][kr << 2];
            float4 wb = *(const float4*)&w2t[c][kr << 2];
            float xx[4] = {xv.x, xv.y, xv.z, xv.w};
            float w1v[4] = {wa.x, wa.y, wa.z, wa.w};
            float w2v[4] = {wb.x, wb.y, wb.z, wb.w};
            float x2[4], xm[4];
#pragma unroll
            for (int j = 0; j < 4; j++) { x2[j] = xx[j]*xx[j]; xm[j] = -2.f*xx[j]; }
#pragma unroll
            for (int i = 0; i < 4; i++)
#pragma unroll
                for (int j = 0; j < 4; j++) {
                    acc[i][j] = fmaf(x2[j], w1v[i], acc[i][j]);
                    acc[i][j] = fmaf(xm[j], w2v[i], acc[i][j]);
                }
        }
    }
#pragma unroll
    for (int i = 0; i < 4; i++) {
        float4 v = make_float4(acc[i][0], acc[i][1], acc[i][2], acc[i][3]);
        *(float4*)&g_d2p[cs][(b*KK + k0 + kr*4 + i)*HW + n0 + nr*4] = v;
    }
}

// ---------------- K3: softmax over K ----------------
// grid 16 blocks x 256 threads; one (b,n) per thread.
__global__ void k3_softmax(float* __restrict__ soft_out) {
    int b = blockIdx.x >> 2;
    int n = ((blockIdx.x & 3) << 8) + threadIdx.x;
    float v[KK];
    float mx = -3.4e38f;
#pragma unroll
    for (int k = 0; k < KK; k++) {
        int idx = (b*KK + k)*HW + n;
        float d2 = g_d2p[0][idx] + g_d2p[1][idx] + g_ck[k];
        float l = -0.5f * d2;
        v[k] = l;
        mx = fmaxf(mx, l);
    }
    float s = 0.f;
#pragma unroll
    for (int k = 0; k < KK; k++) { v[k] = expf(v[k] - mx); s += v[k]; }
    float is = 1.f / s;
#pragma unroll
    for (int k = 0; k < KK; k++)
        soft_out[(b*KK + k)*HW + n] = v[k] * is;
}

// ---------------- K4: aggregation GEMM ----------------
// grid 128 blocks x 256 threads. Block: all 64 k x 64 c, n-range 256 (split 4).
__global__ void k4_agg(const float* __restrict__ x,
                       const float* __restrict__ soft) {
    int bid = blockIdx.x;
    int ns = bid & 3;
    int ct = (bid >> 2) & 7;
    int b  = bid >> 5;
    int c0 = ct * 64, nb0 = ns * 256;

    __shared__ float xT[32][68];   // [n][c] padded
    __shared__ float sT[32][68];   // [n][k] padded

    int tid = threadIdx.x;
    int kr = tid >> 4;   // 0..15 -> k = kr*4 + i
    int cr = tid & 15;   // 0..15 -> c = c0 + cr*4 + j

    float acc[4][4];
#pragma unroll
    for (int i = 0; i < 4; i++)
#pragma unroll
        for (int j = 0; j < 4; j++) acc[i][j] = 0.f;

    for (int nc = 0; nc < 256; nc += 32) {
        __syncthreads();
#pragma unroll
        for (int l = 0; l < 8; l++) {
            int idx = tid + l * 256;   // 0..2047
            int row = idx >> 5;        // 0..63
            int col = idx & 31;
            xT[col][row] = x[(b*CC + c0 + row)*HW + nb0 + nc + col];
            sT[col][row] = soft[(b*KK + row)*HW + nb0 + nc + col];
        }
        __syncthreads();
#pragma unroll
        for (int n = 0; n < 32; n++) {
            float4 xv = *(const float4*)&xT[n][cr << 2];
            float4 sv = *(const float4*)&sT[n][kr << 2];
            float xj[4] = {xv.x, xv.y, xv.z, xv.w};
            float si[4] = {sv.x, sv.y, sv.z, sv.w};
#pragma unroll
            for (int i = 0; i < 4; i++)
#pragma unroll
                for (int j = 0; j < 4; j++)
                    acc[i][j] = fmaf(si[i], xj[j], acc[i][j]);
        }
    }
#pragma unroll
    for (int i = 0; i < 4; i++) {
        float4 v = make_float4(acc[i][0], acc[i][1], acc[i][2], acc[i][3]);
        *(float4*)&g_nump[ns][(b*KK + kr*4 + i)*CC + c0 + cr*4] = v;
    }
}

// ---------------- K5: epilogue + per-row normalize ----------------
// grid 256 blocks x 256 threads; one (b,k) per block.
__global__ void k5_epilogue(const float* __restrict__ soft,
                            const float* __restrict__ anchor,
                            float* __restrict__ out) {
    int bk = blockIdx.x;            // b*64 + k
    int k  = bk & 63;
    int tid = threadIdx.x;
    __shared__ float red[256];

    // wsum[b,k] = sum_n soft
    const float* srow = soft + bk * HW;
    float ws = 0.f;
    for (int n = tid; n < HW; n += 256) ws += srow[n];
    red[tid] = ws; __syncthreads();
    for (int s = 128; s > 0; s >>= 1) {
        if (tid < s) red[tid] += red[tid + s];
        __syncthreads();
    }
    ws = red[0];
    __syncthreads();

    float invden = 1.f / (ws + 1e-7f);
    float node[2];
    float sq = 0.f;
#pragma unroll
    for (int l = 0; l < 2; l++) {
        int c = tid + l * 256;
        int gi = bk * CC + c;
        float num = g_nump[0][gi] + g_nump[1][gi] + g_nump[2][gi] + g_nump[3][gi];
        num = (num - ws * anchor[k*CC + c]) * g_inv[k*CC + c];
        float nd = num * invden;
        node[l] = nd;
        sq += nd * nd;
    }
    red[tid] = sq; __syncthreads();
    for (int s = 128; s > 0; s >>= 1) {
        if (tid < s) red[tid] += red[tid + s];
        __syncthreads();
    }
    float total = red[0];
    float nrm = sqrtf(total);
    float scale = 1.f / fmaxf(nrm, 1e-12f);
#pragma unroll
    for (int l = 0; l < 2; l++)
        out[bk * CC + tid + l * 256] = node[l] * scale;
    if (tid == 0) g_rowsq[bk] = total * scale * scale;
}

// ---------------- K6: flat normalize per b ----------------
__global__ void k6_final(float* __restrict__ out) {
    int b = blockIdx.x;
    int tid = threadIdx.x;
    __shared__ float red[64];
    __shared__ float sc;
    if (tid < 64) red[tid] = g_rowsq[b*64 + tid];
    __syncthreads();
    if (tid == 0) {
        float s = 0.f;
        for (int i = 0; i < 64; i++) s += red[i];
        sc = 1.f / fmaxf(sqrtf(s), 1e-12f);
    }
    __syncthreads();
    float scale = sc;
    float4* o = (float4*)(out + b * (KK*CC));
    for (int i = tid; i < (KK*CC)/4; i += 256) {
        float4 v = o[i];
        v.x *= scale; v.y *= scale; v.z *= scale; v.w *= scale;
        o[i] = v;
    }
}

// ---------------- launch ----------------
extern "C" void kernel_launch(void* const* d_in, const int* in_sizes, int n_in,
                              void* d_out, int out_size) {
    const float* x      = (const float*)d_in[0];
    const float* anchor = (const float*)d_in[1];
    const float* sigma  = (const float*)d_in[2];
    float* out = (float*)d_out;
    float* nodes_out = out;                 // B*K*C floats (== flat.reshape(B,C,K))
    float* soft_out  = out + BB*KK*CC;      // B*K*HW floats

    k1_prep   <<<KK, 256>>>(anchor, sigma);
    k2_dist   <<<256, 128>>>(x);
    k3_softmax<<<16, 256>>>(soft_out);
    k4_agg    <<<128, 256>>>(x, soft_out);
    k5_epilogue<<<BB*KK, 256>>>(soft_out, anchor, nodes_out);
    k6_final  <<<BB, 256>>>(nodes_out);
}

// round 2
// speedup vs baseline: 1.0799x; 1.0799x over previous
#include <cuda_runtime.h>
#include <math.h>

#define BB 4
#define CC 512
#define HW 1024
#define KK 64

typedef unsigned long long u64;

// ---------------- scratch ----------------
__device__ float g_w1t[CC*KK];          // inv2, c-major [c][k]
__device__ float g_w2t[CC*KK];          // -2*anchor*inv2, c-major [c][k]
__device__ float g_inv[KK*CC];          // inv, k-major
__device__ float g_ck[KK];              // sum_c anchor^2*inv2
__device__ float g_d2p[8][BB*KK*HW];    // partial d2 (C split 8)
__device__ float g_nump[16][BB*KK*CC];  // partial aggregation (n split 16)
__device__ float g_rowsq[BB*KK];

// ---------------- f32x2 helpers ----------------
__device__ __forceinline__ u64 pack2(float a, float b) {
    u64 r; asm("mov.b64 %0, {%1, %2};" : "=l"(r) : "f"(a), "f"(b)); return r;
}
__device__ __forceinline__ u64 dup2(float a) {
    u64 r; asm("mov.b64 %0, {%1, %1};" : "=l"(r) : "f"(a)); return r;
}
__device__ __forceinline__ void fma2(u64& d, u64 a, u64 b) {
    asm("fma.rn.f32x2 %0, %1, %2, %0;" : "+l"(d) : "l"(a), "l"(b));
}
__device__ __forceinline__ u64 mul2(u64 a, u64 b) {
    u64 r; asm("mul.rn.f32x2 %0, %1, %2;" : "=l"(r) : "l"(a), "l"(b)); return r;
}
__device__ __forceinline__ float2 unpk(u64 a) {
    float x, y; asm("mov.b64 {%0, %1}, %2;" : "=f"(x), "=f"(y) : "l"(a));
    return make_float2(x, y);
}

// ---------------- K1: weights prep ----------------
__global__ void k1_prep(const float* __restrict__ anchor,
                        const float* __restrict__ sigma) {
    int k = blockIdx.x;
    int tid = threadIdx.x;
    __shared__ float red[256];
    float ck = 0.f;
    for (int c = tid; c < CC; c += 256) {
        int idx = k*CC + c;
        float s  = 1.f / (1.f + expf(-sigma[idx]));
        float iv = 1.f / (s + 1e-7f);
        float i2 = iv * iv;
        float a  = anchor[idx];
        g_w1t[c*KK + k] = i2;
        g_w2t[c*KK + k] = -2.f * a * i2;
        g_inv[idx] = iv;
        ck += a * a * i2;
    }
    red[tid] = ck; __syncthreads();
    for (int s = 128; s > 0; s >>= 1) {
        if (tid < s) red[tid] += red[tid + s];
        __syncthreads();
    }
    if (tid == 0) g_ck[k] = red[0];
}

// ---------------- K2: distance GEMM (f32x2) ----------------
// grid 256 = 4b x 8nt x 8cs, 256 threads. Block tile: 64k x 128n x 64c.
// Thread tile: 4k x 8n (pairs along n: n = nr*4 + q*64, q in {0,1}).
__global__ void __launch_bounds__(256, 2) k2_dist(const float* __restrict__ x) {
    int bid = blockIdx.x;
    int cs = bid & 7;
    int nt = (bid >> 3) & 7;
    int b  = bid >> 6;
    int c0 = cs * 64, n0 = nt * 128;

    __shared__ float xs[16][132];
    __shared__ float w1s[16][68];
    __shared__ float w2s[16][68];

    int tid = threadIdx.x;
    int kr = tid >> 4;     // 0..15 -> k = kr*4 + i
    int nr = tid & 15;     // 0..15 -> n = nr*4 + q*64

    u64 acc[4][4];
#pragma unroll
    for (int i = 0; i < 4; i++)
#pragma unroll
        for (int j = 0; j < 4; j++) acc[i][j] = 0ull;

    for (int cc = 0; cc < 64; cc += 16) {
        __syncthreads();
        // x: 16 c-rows x 128 n, coalesced float4
#pragma unroll
        for (int l = 0; l < 2; l++) {
            int idx = tid + l * 256;          // 0..511 float4 slots
            int row = idx >> 5;
            int col = (idx & 31) << 2;
            *(float4*)&xs[row][col] =
                *(const float4*)&x[(b*CC + c0 + cc + row)*HW + n0 + col];
        }
        // weights (c-major in gmem -> direct coalesced)
#pragma unroll
        for (int l = 0; l < 4; l++) {
            int idx = tid + l * 256;          // 0..1023
            int rc  = idx >> 6;
            int kk  = idx & 63;
            int g   = (c0 + cc + rc)*KK + kk;
            w1s[rc][kk] = g_w1t[g];
            w2s[rc][kk] = g_w2t[g];
        }
        __syncthreads();
#pragma unroll
        for (int c = 0; c < 16; c++) {
            const float4* xr = (const float4*)&xs[c][0];
            float4 xa = xr[nr];
            float4 xb = xr[nr + 16];
            u64 xp0 = pack2(xa.x, xa.y), xp1 = pack2(xa.z, xa.w);
            u64 xp2 = pack2(xb.x, xb.y), xp3 = pack2(xb.z, xb.w);
            u64 xq0 = mul2(xp0, xp0), xq1 = mul2(xp1, xp1);
            u64 xq2 = mul2(xp2, xp2), xq3 = mul2(xp3, xp3);
            float4 w1v = *(const float4*)&w1s[c][kr << 2];
            float4 w2v = *(const float4*)&w2s[c][kr << 2];
            const float* w1p = (const float*)&w1v;
            const float* w2p = (const float*)&w2v;
#pragma unroll
            for (int i = 0; i < 4; i++) {
                u64 w1d = dup2(w1p[i]);
                u64 w2d = dup2(w2p[i]);
                fma2(acc[i][0], xq0, w1d); fma2(acc[i][0], xp0, w2d);
                fma2(acc[i][1], xq1, w1d); fma2(acc[i][1], xp1, w2d);
                fma2(acc[i][2], xq2, w1d); fma2(acc[i][2], xp2, w2d);
                fma2(acc[i][3], xq3, w1d); fma2(acc[i][3], xp3, w2d);
            }
        }
    }
#pragma unroll
    for (int i = 0; i < 4; i++) {
        int k = kr*4 + i;
        float2 p0 = unpk(acc[i][0]), p1 = unpk(acc[i][1]);
        float2 p2 = unpk(acc[i][2]), p3 = unpk(acc[i][3]);
        int base = (b*KK + k)*HW + n0 + nr*4;
        *(float4*)&g_d2p[cs][base]      = make_float4(p0.x, p0.y, p1.x, p1.y);
        *(float4*)&g_d2p[cs][base + 64] = make_float4(p2.x, p2.y, p3.x, p3.y);
    }
}

// ---------------- K3: softmax over K ----------------
// grid 128 x 32; one (b,n) per thread.
__global__ void k3_softmax(float* __restrict__ soft_out) {
    int pos = blockIdx.x * 32 + threadIdx.x;   // 0..4095
    int b = pos >> 10;
    int n = pos & 1023;
    float v[KK];
    float mx = -3.4e38f;
#pragma unroll
    for (int k = 0; k < KK; k++) {
        int idx = (b*KK + k)*HW + n;
        float d = g_ck[k];
#pragma unroll
        for (int p = 0; p < 8; p++) d += g_d2p[p][idx];
        float l = -0.5f * d;
        v[k] = l;
        mx = fmaxf(mx, l);
    }
    float s = 0.f;
#pragma unroll
    for (int k = 0; k < KK; k++) { v[k] = __expf(v[k] - mx); s += v[k]; }
    float is = 1.f / s;
#pragma unroll
    for (int k = 0; k < KK; k++)
        soft_out[(b*KK + k)*HW + n] = v[k] * is;
}

// ---------------- K4: aggregation GEMM (f32x2) ----------------
// grid 256 = 4b x 4ct x 16ns, 256 threads. Block tile: 64k x 128c x 64n.
// Thread tile: 4k x 8c (pairs along c: c = cr*4 + q*64).
__global__ void __launch_bounds__(256, 2) k4_agg(const float* __restrict__ x,
                                                 const float* __restrict__ soft) {
    int bid = blockIdx.x;
    int ns = bid & 15;
    int ct = (bid >> 4) & 3;
    int b  = bid >> 6;
    int c0 = ct * 128, n0 = ns * 64;

    __shared__ float xs[16][132];   // [n][c]
    __shared__ float ss[16][68];    // [n][k]

    int tid = threadIdx.x;
    int kr = tid >> 4;   // 0..15 -> k = kr*4 + i
    int cr = tid & 15;   // 0..15 -> c = c0 + cr*4 + q*64

    u64 acc[4][4];
#pragma unroll
    for (int i = 0; i < 4; i++)
#pragma unroll
        for (int j = 0; j < 4; j++) acc[i][j] = 0ull;

    for (int nn = 0; nn < 64; nn += 16) {
        __syncthreads();
        // x chunk: 128 c-rows x 16 n -> transpose into xs[n][c] (float4 gmem reads)
#pragma unroll
        for (int l = 0; l < 2; l++) {
            int idx = tid + l * 256;            // 0..511 float4 slots
            int c   = idx >> 2;                 // 0..127
            int nq  = (idx & 3) << 2;           // 0,4,8,12
            float4 v = *(const float4*)&x[(b*CC + c0 + c)*HW + n0 + nn + nq];
            xs[nq + 0][c] = v.x;
            xs[nq + 1][c] = v.y;
            xs[nq + 2][c] = v.z;
            xs[nq + 3][c] = v.w;
        }
        // soft chunk: 64 k-rows x 16 n -> ss[n][k]
        {
            int idx = tid;                      // 0..255 float4 slots
            int k   = idx >> 2;
            int nq  = (idx & 3) << 2;
            float4 v = *(const float4*)&soft[(b*KK + k)*HW + n0 + nn + nq];
            ss[nq + 0][k] = v.x;
            ss[nq + 1][k] = v.y;
            ss[nq + 2][k] = v.z;
            ss[nq + 3][k] = v.w;
        }
        __syncthreads();
#pragma unroll
        for (int n = 0; n < 16; n++) {
            float4 sv = *(const float4*)&ss[n][kr << 2];
            const float* sp = (const float*)&sv;
            const float4* xr = (const float4*)&xs[n][0];
            float4 xa = xr[cr];
            float4 xb = xr[cr + 16];
            u64 xp0 = pack2(xa.x, xa.y), xp1 = pack2(xa.z, xa.w);
            u64 xp2 = pack2(xb.x, xb.y), xp3 = pack2(xb.z, xb.w);
#pragma unroll
            for (int i = 0; i < 4; i++) {
                u64 sd = dup2(sp[i]);
                fma2(acc[i][0], xp0, sd);
                fma2(acc[i][1], xp1, sd);
                fma2(acc[i][2], xp2, sd);
                fma2(acc[i][3], xp3, sd);
            }
        }
    }
#pragma unroll
    for (int i = 0; i < 4; i++) {
        int k = kr*4 + i;
        float2 p0 = unpk(acc[i][0]), p1 = unpk(acc[i][1]);
        float2 p2 = unpk(acc[i][2]), p3 = unpk(acc[i][3]);
        int base = (b*KK + k)*CC + c0 + cr*4;
        *(float4*)&g_nump[ns][base]      = make_float4(p0.x, p0.y, p1.x, p1.y);
        *(float4*)&g_nump[ns][base + 64] = make_float4(p2.x, p2.y, p3.x, p3.y);
    }
}

// ---------------- K5: epilogue + per-row normalize ----------------
__global__ void k5_epilogue(const float* __restrict__ soft,
                            const float* __restrict__ anchor,
                            float* __restrict__ out) {
    int bk = blockIdx.x;            // b*64 + k
    int k  = bk & 63;
    int tid = threadIdx.x;
    __shared__ float red[256];

    const float* srow = soft + bk * HW;
    float ws = 0.f;
    for (int n = tid; n < HW; n += 256) ws += srow[n];
    red[tid] = ws; __syncthreads();
    for (int s = 128; s > 0; s >>= 1) {
        if (tid < s) red[tid] += red[tid + s];
        __syncthreads();
    }
    ws = red[0];
    __syncthreads();

    float invden = 1.f / (ws + 1e-7f);
    float node[2];
    float sq = 0.f;
#pragma unroll
    for (int l = 0; l < 2; l++) {
        int c = tid + l * 256;
        int gi = bk * CC + c;
        float num = 0.f;
#pragma unroll
        for (int p = 0; p < 16; p++) num += g_nump[p][gi];
        num = (num - ws * anchor[k*CC + c]) * g_inv[k*CC + c];
        float nd = num * invden;
        node[l] = nd;
        sq += nd * nd;
    }
    red[tid] = sq; __syncthreads();
    for (int s = 128; s > 0; s >>= 1) {
        if (tid < s) red[tid] += red[tid + s];
        __syncthreads();
    }
    float total = red[0];
    float scale = 1.f / fmaxf(sqrtf(total), 1e-12f);
#pragma unroll
    for (int l = 0; l < 2; l++)
        out[bk * CC + tid + l * 256] = node[l] * scale;
    if (tid == 0) g_rowsq[bk] = total * scale * scale;
}

// ---------------- K6: flat normalize per b ----------------
__global__ void k6_final(float* __restrict__ out) {
    int b = blockIdx.x;
    int tid = threadIdx.x;
    __shared__ float red[64];
    __shared__ float sc;
    if (tid < 64) red[tid] = g_rowsq[b*64 + tid];
    __syncthreads();
    if (tid == 0) {
        float s = 0.f;
        for (int i = 0; i < 64; i++) s += red[i];
        sc = 1.f / fmaxf(sqrtf(s), 1e-12f);
    }
    __syncthreads();
    float scale = sc;
    float4* o = (float4*)(out + b * (KK*CC));
    for (int i = tid; i < (KK*CC)/4; i += 256) {
        float4 v = o[i];
        v.x *= scale; v.y *= scale; v.z *= scale; v.w *= scale;
        o[i] = v;
    }
}

// ---------------- launch ----------------
extern "C" void kernel_launch(void* const* d_in, const int* in_sizes, int n_in,
                              void* d_out, int out_size) {
    const float* x      = (const float*)d_in[0];
    const float* anchor = (const float*)d_in[1];
    const float* sigma  = (const float*)d_in[2];
    float* out = (float*)d_out;
    float* nodes_out = out;                 // B*K*C floats (== flat.reshape(B,C,K))
    float* soft_out  = out + BB*KK*CC;      // B*K*HW floats

    k1_prep    <<<KK, 256>>>(anchor, sigma);
    k2_dist    <<<256, 256>>>(x);
    k3_softmax <<<128, 32>>>(soft_out);
    k4_agg     <<<256, 256>>>(x, soft_out);
    k5_epilogue<<<BB*KK, 256>>>(soft_out, anchor, nodes_out);
    k6_final   <<<BB, 256>>>(nodes_out);
}

// round 3
// speedup vs baseline: 1.2182x; 1.1280x over previous
#include <cuda_runtime.h>
#include <math.h>

#define BB 4
#define CC 512
#define HW 1024
#define KK 64
#define NP2 16   // d2 partial count (C-split)
#define NP4 32   // agg partial count (n-split)

typedef unsigned long long u64;

// ---------------- scratch ----------------
__device__ float g_w1t[CC*KK];            // inv2, c-major [c][k]
__device__ float g_w2t[CC*KK];            // -2*anchor*inv2, c-major [c][k]
__device__ float g_inv[KK*CC];            // inv, k-major
__device__ float g_ck[KK];                // sum_c anchor^2*inv2
__device__ float g_d2p[NP2][BB*KK*HW];    // d2 partials, k-major
__device__ float g_logits[BB*HW*KK];      // -0.5*(d2+ck), [b][n][k]
__device__ float g_nump[NP4][BB*KK*CC];   // agg partials

// ---------------- f32x2 helpers ----------------
__device__ __forceinline__ u64 pack2(float a, float b) {
    u64 r; asm("mov.b64 %0, {%1, %2};" : "=l"(r) : "f"(a), "f"(b)); return r;
}
__device__ __forceinline__ u64 dup2(float a) {
    u64 r; asm("mov.b64 %0, {%1, %1};" : "=l"(r) : "f"(a)); return r;
}
__device__ __forceinline__ void fma2(u64& d, u64 a, u64 b) {
    asm("fma.rn.f32x2 %0, %1, %2, %0;" : "+l"(d) : "l"(a), "l"(b));
}
__device__ __forceinline__ u64 mul2(u64 a, u64 b) {
    u64 r; asm("mul.rn.f32x2 %0, %1, %2;" : "=l"(r) : "l"(a), "l"(b)); return r;
}
__device__ __forceinline__ float2 unpk(u64 a) {
    float x, y; asm("mov.b64 {%0, %1}, %2;" : "=f"(x), "=f"(y) : "l"(a));
    return make_float2(x, y);
}

// ---------------- K1: weights prep ----------------
__global__ void k1_prep(const float* __restrict__ anchor,
                        const float* __restrict__ sigma) {
    int k = blockIdx.x;
    int tid = threadIdx.x;
    __shared__ float red[256];
    float ck = 0.f;
    for (int c = tid; c < CC; c += 256) {
        int idx = k*CC + c;
        float s  = 1.f / (1.f + expf(-sigma[idx]));
        float iv = 1.f / (s + 1e-7f);
        float i2 = iv * iv;
        float a  = anchor[idx];
        g_w1t[c*KK + k] = i2;
        g_w2t[c*KK + k] = -2.f * a * i2;
        g_inv[idx] = iv;
        ck += a * a * i2;
    }
    red[tid] = ck; __syncthreads();
    for (int s = 128; s > 0; s >>= 1) {
        if (tid < s) red[tid] += red[tid + s];
        __syncthreads();
    }
    if (tid == 0) g_ck[k] = red[0];
}

// ---------------- K2: distance GEMM ----------------
// grid 256 = 4b x 4nt x 16cs, 256 thr. Block: 64k x 256n x 32c. Thread: 8k x 8n.
__global__ void __launch_bounds__(256, 2) k2_dist(const float* __restrict__ x) {
    int bid = blockIdx.x;
    int cs = bid & 15;
    int nt = (bid >> 4) & 3;
    int b  = bid >> 6;
    int c0 = cs * 32, n0 = nt * 256;

    __shared__ float xs[16][264];
    __shared__ float w1s[16][72];
    __shared__ float w2s[16][72];

    int tid = threadIdx.x;
    int kr = tid >> 5;     // 0..7 -> k = kr*8 + i
    int nr = tid & 31;     // n = nr*4 + q*128

    u64 acc[8][4];
#pragma unroll
    for (int i = 0; i < 8; i++)
#pragma unroll
        for (int j = 0; j < 4; j++) acc[i][j] = 0ull;

#pragma unroll
    for (int cc = 0; cc < 32; cc += 16) {
        __syncthreads();
#pragma unroll
        for (int l = 0; l < 4; l++) {
            int idx = tid + l * 256;          // 1024 f4 slots
            int row = idx >> 6;
            int col = (idx & 63) << 2;
            *(float4*)&xs[row][col] =
                *(const float4*)&x[(b*CC + c0 + cc + row)*HW + n0 + col];
        }
        {
            int rc = tid >> 4;                // 256 f4 slots each
            int kk = (tid & 15) << 2;
            int g  = (c0 + cc + rc)*KK + kk;
            *(float4*)&w1s[rc][kk] = *(const float4*)&g_w1t[g];
            *(float4*)&w2s[rc][kk] = *(const float4*)&g_w2t[g];
        }
        __syncthreads();
#pragma unroll
        for (int c = 0; c < 16; c++) {
            const float4* xr = (const float4*)&xs[c][0];
            float4 xa = xr[nr];
            float4 xb = xr[nr + 32];
            u64 xp0 = pack2(xa.x, xa.y), xp1 = pack2(xa.z, xa.w);
            u64 xp2 = pack2(xb.x, xb.y), xp3 = pack2(xb.z, xb.w);
            u64 xq0 = mul2(xp0, xp0), xq1 = mul2(xp1, xp1);
            u64 xq2 = mul2(xp2, xp2), xq3 = mul2(xp3, xp3);
            float4 wa0 = *(const float4*)&w1s[c][kr*8];
            float4 wa1 = *(const float4*)&w1s[c][kr*8 + 4];
            float4 wb0 = *(const float4*)&w2s[c][kr*8];
            float4 wb1 = *(const float4*)&w2s[c][kr*8 + 4];
            const float* w1p0 = (const float*)&wa0;
            const float* w1p1 = (const float*)&wa1;
            const float* w2p0 = (const float*)&wb0;
            const float* w2p1 = (const float*)&wb1;
#pragma unroll
            for (int i = 0; i < 8; i++) {
                float w1f = (i < 4) ? w1p0[i & 3] : w1p1[i & 3];
                float w2f = (i < 4) ? w2p0[i & 3] : w2p1[i & 3];
                u64 w1d = dup2(w1f);
                u64 w2d = dup2(w2f);
                fma2(acc[i][0], xq0, w1d); fma2(acc[i][0], xp0, w2d);
                fma2(acc[i][1], xq1, w1d); fma2(acc[i][1], xp1, w2d);
                fma2(acc[i][2], xq2, w1d); fma2(acc[i][2], xp2, w2d);
                fma2(acc[i][3], xq3, w1d); fma2(acc[i][3], xp3, w2d);
            }
        }
    }
    // coalesced k-major writes
#pragma unroll
    for (int i = 0; i < 8; i++) {
        int k = kr*8 + i;
#pragma unroll
        for (int q = 0; q < 2; q++) {
            float2 a0 = unpk(acc[i][q*2]);
            float2 a1 = unpk(acc[i][q*2 + 1]);
            *(float4*)&g_d2p[cs][(b*KK + k)*HW + n0 + nr*4 + q*128] =
                make_float4(a0.x, a0.y, a1.x, a1.y);
        }
    }
}

// ---------------- K2b: reduce partials + fold ck + transpose to [b][n][k] ----------------
// grid 64 = 4b x 16 n-tiles(64), 256 thr.
__global__ void k2b_red() {
    int b  = blockIdx.x >> 4;
    int n0 = (blockIdx.x & 15) * 64;
    int tid = threadIdx.x;
    __shared__ float sm[64][68];   // [k][n]

#pragma unroll
    for (int l = 0; l < 4; l++) {
        int idx = tid + l * 256;   // 1024 f4 slots: 64k x 16 n-f4
        int k   = idx >> 4;
        int n4  = (idx & 15) << 2;
        int base = (b*KK + k)*HW + n0 + n4;
        float4 s = make_float4(0.f, 0.f, 0.f, 0.f);
#pragma unroll
        for (int p = 0; p < NP2; p++) {
            float4 v = *(const float4*)&g_d2p[p][base];
            s.x += v.x; s.y += v.y; s.z += v.z; s.w += v.w;
        }
        float ck = g_ck[k];
        s.x = -0.5f*(s.x + ck); s.y = -0.5f*(s.y + ck);
        s.z = -0.5f*(s.z + ck); s.w = -0.5f*(s.w + ck);
        *(float4*)&sm[k][n4] = s;
    }
    __syncthreads();
#pragma unroll
    for (int l = 0; l < 4; l++) {
        int idx = tid + l * 256;   // 1024 f4 slots: 64n x 16 k-f4
        int n   = idx >> 4;
        int k4  = (idx & 15) << 2;
        float4 v = make_float4(sm[k4][n], sm[k4+1][n], sm[k4+2][n], sm[k4+3][n]);
        *(float4*)&g_logits[(b*HW + n0 + n)*KK + k4] = v;
    }
}

// ---------------- K3: softmax over K ----------------
// grid 64 x 64; one (b,n) per thread; logits contiguous in k.
__global__ void k3_softmax(float* __restrict__ soft_out) {
    int pos = blockIdx.x * 64 + threadIdx.x;
    int b = pos >> 10;
    int n = pos & 1023;
    const float4* L = (const float4*)&g_logits[(b*HW + n)*KK];
    float v[KK];
    float mx = -3.4e38f;
#pragma unroll
    for (int t = 0; t < 16; t++) {
        float4 l4 = L[t];
        v[t*4+0] = l4.x; v[t*4+1] = l4.y; v[t*4+2] = l4.z; v[t*4+3] = l4.w;
        mx = fmaxf(mx, fmaxf(fmaxf(l4.x, l4.y), fmaxf(l4.z, l4.w)));
    }
    float s = 0.f;
#pragma unroll
    for (int k = 0; k < KK; k++) { v[k] = __expf(v[k] - mx); s += v[k]; }
    float is = 1.f / s;
#pragma unroll
    for (int k = 0; k < KK; k++)
        soft_out[(b*KK + k)*HW + n] = v[k] * is;
}

// ---------------- K4: aggregation GEMM ----------------
// grid 256 = 4b x 2ct x 32ns, 256 thr. Block: 64k x 256c x 32n. Thread: 8k x 8c.
__global__ void __launch_bounds__(256, 2) k4_agg(const float* __restrict__ x,
                                                 const float* __restrict__ soft) {
    int bid = blockIdx.x;
    int ns = bid & 31;
    int ct = (bid >> 5) & 1;
    int b  = bid >> 6;
    int c0 = ct * 256, n0 = ns * 32;

    __shared__ float xs[16][268];   // [n][c 256]
    __shared__ float ss[16][76];    // [n][k 64]

    int tid = threadIdx.x;
    int kr = tid >> 5;   // 0..7 -> k = kr*8 + i
    int cr = tid & 31;   // c = c0 + cr*4 + q*128

    u64 acc[8][4];
#pragma unroll
    for (int i = 0; i < 8; i++)
#pragma unroll
        for (int j = 0; j < 4; j++) acc[i][j] = 0ull;

#pragma unroll
    for (int nn = 0; nn < 32; nn += 16) {
        __syncthreads();
#pragma unroll
        for (int l = 0; l < 4; l++) {
            int idx = tid + l * 256;            // 1024 f4 slots: 256c x 4 n-f4
            int c   = idx >> 2;
            int nq  = (idx & 3) << 2;
            float4 v = *(const float4*)&x[(b*CC + c0 + c)*HW + n0 + nn + nq];
            xs[nq + 0][c] = v.x;
            xs[nq + 1][c] = v.y;
            xs[nq + 2][c] = v.z;
            xs[nq + 3][c] = v.w;
        }
        {
            int k  = tid >> 2;                  // 256 f4 slots: 64k x 4 n-f4
            int nq = (tid & 3) << 2;
            float4 v = *(const float4*)&soft[(b*KK + k)*HW + n0 + nn + nq];
            ss[nq + 0][k] = v.x;
            ss[nq + 1][k] = v.y;
            ss[nq + 2][k] = v.z;
            ss[nq + 3][k] = v.w;
        }
        __syncthreads();
#pragma unroll
        for (int n = 0; n < 16; n++) {
            float4 sa = *(const float4*)&ss[n][kr*8];
            float4 sb = *(const float4*)&ss[n][kr*8 + 4];
            const float* sp0 = (const float*)&sa;
            const float* sp1 = (const float*)&sb;
            const float4* xr = (const float4*)&xs[n][0];
            float4 xa = xr[cr];
            float4 xb = xr[cr + 32];
            u64 xp0 = pack2(xa.x, xa.y), xp1 = pack2(xa.z, xa.w);
            u64 xp2 = pack2(xb.x, xb.y), xp3 = pack2(xb.z, xb.w);
#pragma unroll
            for (int i = 0; i < 8; i++) {
                float sf = (i < 4) ? sp0[i & 3] : sp1[i & 3];
                u64 sd = dup2(sf);
                fma2(acc[i][0], xp0, sd);
                fma2(acc[i][1], xp1, sd);
                fma2(acc[i][2], xp2, sd);
                fma2(acc[i][3], xp3, sd);
            }
        }
    }
#pragma unroll
    for (int i = 0; i < 8; i++) {
        int k = kr*8 + i;
#pragma unroll
        for (int q = 0; q < 2; q++) {
            float2 a0 = unpk(acc[i][q*2]);
            float2 a1 = unpk(acc[i][q*2 + 1]);
            *(float4*)&g_nump[ns][(b*KK + k)*CC + c0 + cr*4 + q*128] =
                make_float4(a0.x, a0.y, a1.x, a1.y);
        }
    }
}

// ---------------- K5: epilogue + row normalize + folded flat normalize ----------------
__global__ void k5_epilogue(const float* __restrict__ soft,
                            const float* __restrict__ anchor,
                            float* __restrict__ out) {
    int bk = blockIdx.x;            // b*64 + k
    int k  = bk & 63;
    int tid = threadIdx.x;
    __shared__ float red[256];

    const float* srow = soft + bk * HW;
    float ws = 0.f;
    for (int n = tid; n < HW; n += 256) ws += srow[n];
    red[tid] = ws; __syncthreads();
    for (int s = 128; s > 0; s >>= 1) {
        if (tid < s) red[tid] += red[tid + s];
        __syncthreads();
    }
    ws = red[0];
    __syncthreads();

    float invden = 1.f / (ws + 1e-7f);
    float node[2];
    float sq = 0.f;
#pragma unroll
    for (int l = 0; l < 2; l++) {
        int c = tid + l * 256;
        int gi = bk * CC + c;
        float num = 0.f;
#pragma unroll
        for (int p = 0; p < NP4; p++) num += g_nump[p][gi];
        num = (num - ws * anchor[k*CC + c]) * g_inv[k*CC + c];
        float nd = num * invden;
        node[l] = nd;
        sq += nd * nd;
    }
    red[tid] = sq; __syncthreads();
    for (int s = 128; s > 0; s >>= 1) {
        if (tid < s) red[tid] += red[tid + s];
        __syncthreads();
    }
    float total = red[0];
    // per-row normalize; flat normalize folded as 1/sqrt(64) (each row has unit norm)
    float scale = 0.125f / fmaxf(sqrtf(total), 1e-12f);
#pragma unroll
    for (int l = 0; l < 2; l++)
        out[bk * CC + tid + l * 256] = node[l] * scale;
}

// ---------------- launch ----------------
extern "C" void kernel_launch(void* const* d_in, const int* in_sizes, int n_in,
                              void* d_out, int out_size) {
    const float* x      = (const float*)d_in[0];
    const float* anchor = (const float*)d_in[1];
    const float* sigma  = (const float*)d_in[2];
    float* out = (float*)d_out;
    float* nodes_out = out;                 // B*K*C floats
    float* soft_out  = out + BB*KK*CC;      // B*K*HW floats

    k1_prep    <<<KK, 256>>>(anchor, sigma);
    k2_dist    <<<256, 256>>>(x);
    k2b_red    <<<64, 256>>>();
    k3_softmax <<<64, 64>>>(soft_out);
    k4_agg     <<<256, 256>>>(x, soft_out);
    k5_epilogue<<<BB*KK, 256>>>(soft_out, anchor, nodes_out);
}

// round 5
// speedup vs baseline: 1.4666x; 1.2039x over previous
#include <cuda_runtime.h>
#include <math.h>

#define BB 4
#define CC 512
#define HW 1024
#define KK 64
#define NP2 16   // d2 partial count (C-split)
#define NP4 32   // agg partial count (n-split)
#define NWT 32   // wsum partial tiles

typedef unsigned long long u64;

// ---------------- scratch ----------------
__device__ float g_w1t[CC*KK];            // inv2, c-major [c][k]
__device__ float g_w2t[CC*KK];            // -2*anchor*inv2, c-major [c][k]
__device__ float g_inv[KK*CC];            // inv, k-major
__device__ float g_ck[KK];                // sum_c anchor^2*inv2
__device__ float g_d2p[NP2][BB*KK*HW];    // d2 partials, k-major
__device__ float g_nump[NP4][BB*KK*CC];   // agg partials
__device__ float g_wsp[BB*NWT*KK];        // wsum partials

// ---------------- f32x2 helpers ----------------
__device__ __forceinline__ u64 dup2(float a) {
    u64 r; asm("mov.b64 %0, {%1, %1};" : "=l"(r) : "f"(a)); return r;
}
__device__ __forceinline__ void fma2(u64& d, u64 a, u64 b) {
    asm("fma.rn.f32x2 %0, %1, %2, %0;" : "+l"(d) : "l"(a), "l"(b));
}
__device__ __forceinline__ u64 mul2(u64 a, u64 b) {
    u64 r; asm("mul.rn.f32x2 %0, %1, %2;" : "=l"(r) : "l"(a), "l"(b)); return r;
}
__device__ __forceinline__ float2 unpk(u64 a) {
    float x, y; asm("mov.b64 {%0, %1}, %2;" : "=f"(x), "=f"(y) : "l"(a));
    return make_float2(x, y);
}

// ---------------- K1: weights prep ----------------
__global__ void k1_prep(const float* __restrict__ anchor,
                        const float* __restrict__ sigma) {
    int k = blockIdx.x;
    int tid = threadIdx.x;
    __shared__ float red[256];
    float ck = 0.f;
    for (int c = tid; c < CC; c += 256) {
        int idx = k*CC + c;
        float s  = 1.f / (1.f + expf(-sigma[idx]));
        float iv = 1.f / (s + 1e-7f);
        float i2 = iv * iv;
        float a  = anchor[idx];
        g_w1t[c*KK + k] = i2;
        g_w2t[c*KK + k] = -2.f * a * i2;
        g_inv[idx] = iv;
        ck += a * a * i2;
    }
    red[tid] = ck; __syncthreads();
    for (int s = 128; s > 0; s >>= 1) {
        if (tid < s) red[tid] += red[tid + s];
        __syncthreads();
    }
    if (tid == 0) g_ck[k] = red[0];
}

// ---------------- K2: distance GEMM (k-paired f32x2) ----------------
// grid 256 = 4b x 4nt x 16cs, 256 thr. Block: 64k x 256n x 32c. Thread: 8k x 8n.
__global__ void __launch_bounds__(256, 2) k2_dist(const float* __restrict__ x) {
    int bid = blockIdx.x;
    int cs = bid & 15;
    int nt = (bid >> 4) & 3;
    int b  = bid >> 6;
    int c0 = cs * 32, n0 = nt * 256;

    __shared__ float xs[16][264];
    __shared__ float w1s[16][72];
    __shared__ float w2s[16][72];

    int tid = threadIdx.x;
    int kr = tid >> 5;     // 0..7, warp-uniform -> k0 = kr*8
    int nr = tid & 31;     // n = n0 + nr*4 + {0..3} and +128
    int k0 = kr * 8;

    u64 acc[4][8];         // [k-pair][n-slot]
#pragma unroll
    for (int i = 0; i < 4; i++)
#pragma unroll
        for (int j = 0; j < 8; j++) acc[i][j] = 0ull;

#pragma unroll
    for (int cc = 0; cc < 32; cc += 16) {
        __syncthreads();
#pragma unroll
        for (int l = 0; l < 4; l++) {
            int idx = tid + l * 256;          // 1024 f4 slots
            int row = idx >> 6;
            int col = (idx & 63) << 2;
            *(float4*)&xs[row][col] =
                *(const float4*)&x[(b*CC + c0 + cc + row)*HW + n0 + col];
        }
        {
            int rc = tid >> 4;                // 256 f4 slots each
            int kk = (tid & 15) << 2;
            int g  = (c0 + cc + rc)*KK + kk;
            *(float4*)&w1s[rc][kk] = *(const float4*)&g_w1t[g];
            *(float4*)&w2s[rc][kk] = *(const float4*)&g_w2t[g];
        }
        __syncthreads();
#pragma unroll
        for (int c = 0; c < 16; c++) {
            const float4* xr = (const float4*)&xs[c][0];
            float4 xa = xr[nr];
            float4 xb = xr[nr + 32];
            // weight pairs (warp-uniform address -> smem broadcast)
            ulonglong2 w1a = *(const ulonglong2*)&w1s[c][k0];
            ulonglong2 w1b = *(const ulonglong2*)&w1s[c][k0 + 4];
            ulonglong2 w2a = *(const ulonglong2*)&w2s[c][k0];
            ulonglong2 w2b = *(const ulonglong2*)&w2s[c][k0 + 4];
            u64 w1p[4] = {w1a.x, w1a.y, w1b.x, w1b.y};
            u64 w2p[4] = {w2a.x, w2a.y, w2b.x, w2b.y};
            float xn[8] = {xa.x, xa.y, xa.z, xa.w, xb.x, xb.y, xb.z, xb.w};
#pragma unroll
            for (int j = 0; j < 8; j++) {
                u64 xd = dup2(xn[j]);
                u64 xq = mul2(xd, xd);
#pragma unroll
                for (int kp = 0; kp < 4; kp++) {
                    fma2(acc[kp][j], xq, w1p[kp]);
                    fma2(acc[kp][j], xd, w2p[kp]);
                }
            }
        }
    }
    // stores: regroup k-pairs -> k-major coalesced float4s
#pragma unroll
    for (int kp = 0; kp < 4; kp++) {
        float2 p[8];
#pragma unroll
        for (int j = 0; j < 8; j++) p[j] = unpk(acc[kp][j]);
        int klo = k0 + 2*kp;
        int base = (b*KK + klo)*HW + n0 + nr*4;
        *(float4*)&g_d2p[cs][base]            = make_float4(p[0].x, p[1].x, p[2].x, p[3].x);
        *(float4*)&g_d2p[cs][base + 128]      = make_float4(p[4].x, p[5].x, p[6].x, p[7].x);
        *(float4*)&g_d2p[cs][base + HW]       = make_float4(p[0].y, p[1].y, p[2].y, p[3].y);
        *(float4*)&g_d2p[cs][base + HW + 128] = make_float4(p[4].y, p[5].y, p[6].y, p[7].y);
    }
}

// ---------------- K23: partial reduce + softmax + wsum partials ----------------
// grid 128 = 4b x 32 tiles(32n), 512 thr.
__global__ void __launch_bounds__(512, 2) k23(float* __restrict__ soft_out) {
    int b    = blockIdx.x >> 5;
    int tile = blockIdx.x & 31;
    int n0   = tile * 32;
    int tid  = threadIdx.x;
    __shared__ float sm[64][36];   // [k][n]

    // phase 1: reduce 16 partials, fold ck and -0.5 -> logits in smem
    {
        int k  = tid >> 3;          // 0..63
        int n4 = (tid & 7) << 2;    // 0..28
        int base = (b*KK + k)*HW + n0 + n4;
        float4 s = make_float4(0.f, 0.f, 0.f, 0.f);
#pragma unroll
        for (int p = 0; p < NP2; p++) {
            float4 v = *(const float4*)&g_d2p[p][base];
            s.x += v.x; s.y += v.y; s.z += v.z; s.w += v.w;
        }
        float ck = g_ck[k];
        s.x = -0.5f*(s.x + ck); s.y = -0.5f*(s.y + ck);
        s.z = -0.5f*(s.z + ck); s.w = -0.5f*(s.w + ck);
        *(float4*)&sm[k][n4] = s;
    }
    __syncthreads();

    // phase 2: softmax over k; 16 threads per position, 4 k each (k = sub + 16*i)
    {
        int n   = tid >> 4;        // 0..31
        int sub = tid & 15;
        float v[4];
        float mx = -3.4e38f;
#pragma unroll
        for (int i = 0; i < 4; i++) {
            v[i] = sm[sub + 16*i][n];
            mx = fmaxf(mx, v[i]);
        }
#pragma unroll
        for (int m = 1; m < 16; m <<= 1)
            mx = fmaxf(mx, __shfl_xor_sync(0xffffffffu, mx, m));
        float s = 0.f;
#pragma unroll
        for (int i = 0; i < 4; i++) { v[i] = __expf(v[i] - mx); s += v[i]; }
#pragma unroll
        for (int m = 1; m < 16; m <<= 1)
            s += __shfl_xor_sync(0xffffffffu, s, m);
        float is = 1.f / s;
#pragma unroll
        for (int i = 0; i < 4; i++)
            sm[sub + 16*i][n] = v[i] * is;
    }
    __syncthreads();

    // phase 3a: coalesced k-major store of soft
    {
        int k  = tid >> 3;
        int n4 = (tid & 7) << 2;
        *(float4*)&soft_out[(b*KK + k)*HW + n0 + n4] = *(const float4*)&sm[k][n4];
    }
    // phase 3b: wsum partials per k over this 32-n tile
    {
        int k   = tid >> 3;        // 0..63
        int sub = tid & 7;         // 4 n each
        float w = 0.f;
#pragma unroll
        for (int j = 0; j < 4; j++) w += sm[k][sub*4 + j];
#pragma unroll
        for (int m = 1; m < 8; m <<= 1)
            w += __shfl_xor_sync(0xffffffffu, w, m);
        if (sub == 0) g_wsp[(b*NWT + tile)*KK + k] = w;
    }
}

// ---------------- K4: aggregation GEMM (c-paired f32x2) ----------------
// grid 256 = 4b x 2ct x 32ns, 256 thr. Block: 64k x 256c x 32n. Thread: 8k x 8c.
__global__ void __launch_bounds__(256, 2) k4_agg(const float* __restrict__ x,
                                                 const float* __restrict__ soft) {
    int bid = blockIdx.x;
    int ns = bid & 31;
    int ct = (bid >> 5) & 1;
    int b  = bid >> 6;
    int c0 = ct * 256, n0 = ns * 32;

    __shared__ float xs[16][268];   // [n][c 256]
    __shared__ float ss[16][76];    // [n][k 64]

    int tid = threadIdx.x;
    int kr = tid >> 5;   // 0..7, warp-uniform -> k0 = kr*8
    int cr = tid & 31;   // c = c0 + cr*4 (+128)
    int k0 = kr * 8;

    u64 acc[8][4];       // [k][c-pair]
#pragma unroll
    for (int i = 0; i < 8; i++)
#pragma unroll
        for (int j = 0; j < 4; j++) acc[i][j] = 0ull;

#pragma unroll
    for (int nn = 0; nn < 32; nn += 16) {
        __syncthreads();
#pragma unroll
        for (int l = 0; l < 4; l++) {
            int idx = tid + l * 256;            // 1024 f4 slots: 256c x 4 n-f4
            int c   = idx >> 2;
            int nq  = (idx & 3) << 2;
            float4 v = *(const float4*)&x[(b*CC + c0 + c)*HW + n0 + nn + nq];
            xs[nq + 0][c] = v.x;
            xs[nq + 1][c] = v.y;
            xs[nq + 2][c] = v.z;
            xs[nq + 3][c] = v.w;
        }
        {
            int k  = tid >> 2;                  // 256 f4 slots: 64k x 4 n-f4
            int nq = (tid & 3) << 2;
            float4 v = *(const float4*)&soft[(b*KK + k)*HW + n0 + nn + nq];
            ss[nq + 0][k] = v.x;
            ss[nq + 1][k] = v.y;
            ss[nq + 2][k] = v.z;
            ss[nq + 3][k] = v.w;
        }
        __syncthreads();
#pragma unroll
        for (int n = 0; n < 16; n++) {
            ulonglong2 xa = *(const ulonglong2*)&xs[n][cr*4];
            ulonglong2 xb = *(const ulonglong2*)&xs[n][cr*4 + 128];
            float4 sa = *(const float4*)&ss[n][k0];       // broadcast
            float4 sb = *(const float4*)&ss[n][k0 + 4];   // broadcast
            float sk[8] = {sa.x, sa.y, sa.z, sa.w, sb.x, sb.y, sb.z, sb.w};
#pragma unroll
            for (int i = 0; i < 8; i++) {
                u64 sd = dup2(sk[i]);
                fma2(acc[i][0], xa.x, sd);
                fma2(acc[i][1], xa.y, sd);
                fma2(acc[i][2], xb.x, sd);
                fma2(acc[i][3], xb.y, sd);
            }
        }
    }
#pragma unroll
    for (int i = 0; i < 8; i++) {
        int k = k0 + i;
        float2 a0 = unpk(acc[i][0]), a1 = unpk(acc[i][1]);
        float2 a2 = unpk(acc[i][2]), a3 = unpk(acc[i][3]);
        int base = (b*KK + k)*CC + c0 + cr*4;
        *(float4*)&g_nump[ns][base]       = make_float4(a0.x, a0.y, a1.x, a1.y);
        *(float4*)&g_nump[ns][base + 128] = make_float4(a2.x, a2.y, a3.x, a3.y);
    }
}

// ---------------- K5: epilogue + row normalize + folded flat normalize ----------------
__global__ void k5_epilogue(const float* __restrict__ anchor,
                            float* __restrict__ out) {
    int bk = blockIdx.x;            // b*64 + k
    int k  = bk & 63;
    int b  = bk >> 6;
    int tid = threadIdx.x;
    __shared__ float red[256];

    float ws = 0.f;
#pragma unroll
    for (int p = 0; p < NWT; p++) ws += g_wsp[(b*NWT + p)*KK + k];

    float invden = 1.f / (ws + 1e-7f);
    float node[2];
    float sq = 0.f;
#pragma unroll
    for (int l = 0; l < 2; l++) {
        int c = tid + l * 256;
        int gi = bk * CC + c;
        float num = 0.f;
#pragma unroll
        for (int p = 0; p < NP4; p++) num += g_nump[p][gi];
        num = (num - ws * anchor[k*CC + c]) * g_inv[k*CC + c];
        float nd = num * invden;
        node[l] = nd;
        sq += nd * nd;
    }
    red[tid] = sq; __syncthreads();
    for (int s = 128; s > 0; s >>= 1) {
        if (tid < s) red[tid] += red[tid + s];
        __syncthreads();
    }
    float total = red[0];
    // per-row normalize; flat normalize folded as 1/sqrt(64) (each row has unit norm)
    float scale = 0.125f / fmaxf(sqrtf(total), 1e-12f);
#pragma unroll
    for (int l = 0; l < 2; l++)
        out[bk * CC + tid + l * 256] = node[l] * scale;
}

// ---------------- launch ----------------
extern "C" void kernel_launch(void* const* d_in, const int* in_sizes, int n_in,
                              void* d_out, int out_size) {
    const float* x      = (const float*)d_in[0];
    const float* anchor = (const float*)d_in[1];
    const float* sigma  = (const float*)d_in[2];
    float* out = (float*)d_out;
    float* nodes_out = out;                 // B*K*C floats
    float* soft_out  = out + BB*KK*CC;      // B*K*HW floats

    k1_prep    <<<KK, 256>>>(anchor, sigma);
    k2_dist    <<<256, 256>>>(x);
    k23        <<<128, 512>>>(soft_out);
    k4_agg     <<<256, 256>>>(x, soft_out);
    k5_epilogue<<<BB*KK, 256>>>(anchor, nodes_out);
}

// round 6
// speedup vs baseline: 1.6435x; 1.1207x over previous
#include <cuda_runtime.h>
#include <math.h>

#define BB 4
#define CC 512
#define HW 1024
#define KK 64
#define NP2 16   // d2 partial count (C-split)
#define NP4 16   // agg partial count (n-split)
#define NWT 32   // wsum partial tiles

typedef unsigned long long u64;
typedef unsigned int u32;

// ---------------- scratch ----------------
__device__ float g_w1t[CC*KK];            // inv2, c-major [c][k]
__device__ float g_w2t[CC*KK];            // -2*anchor*inv2, c-major [c][k]
__device__ float g_inv[KK*CC];            // inv, k-major
__device__ float g_ck[KK];                // sum_c anchor^2*inv2
__device__ float g_d2p[NP2][BB*KK*HW];    // d2 partials, k-major
__device__ float g_nump[NP4][BB*KK*CC];   // agg partials
__device__ float g_wsp[BB*NWT*KK];        // wsum partials

// ---------------- f32x2 helpers ----------------
__device__ __forceinline__ u64 dup2(float a) {
    u64 r; asm("mov.b64 %0, {%1, %1};" : "=l"(r) : "f"(a)); return r;
}
__device__ __forceinline__ void fma2(u64& d, u64 a, u64 b) {
    asm("fma.rn.f32x2 %0, %1, %2, %0;" : "+l"(d) : "l"(a), "l"(b));
}
__device__ __forceinline__ u64 mul2(u64 a, u64 b) {
    u64 r; asm("mul.rn.f32x2 %0, %1, %2;" : "=l"(r) : "l"(a), "l"(b)); return r;
}
__device__ __forceinline__ float2 unpk(u64 a) {
    float x, y; asm("mov.b64 {%0, %1}, %2;" : "=f"(x), "=f"(y) : "l"(a));
    return make_float2(x, y);
}

// ---------------- tf32 mma helpers ----------------
__device__ __forceinline__ u32 tf32cvt(float f) {
    u32 r; asm("cvt.rna.tf32.f32 %0, %1;" : "=r"(r) : "f"(f)); return r;
}
__device__ __forceinline__ void mma_tf32(float& d0, float& d1, float& d2, float& d3,
                                         u32 a0, u32 a1, u32 a2, u32 a3,
                                         u32 b0, u32 b1) {
    asm("mma.sync.aligned.m16n8k8.row.col.f32.tf32.tf32.f32 "
        "{%0,%1,%2,%3},{%4,%5,%6,%7},{%8,%9},{%0,%1,%2,%3};"
        : "+f"(d0), "+f"(d1), "+f"(d2), "+f"(d3)
        : "r"(a0), "r"(a1), "r"(a2), "r"(a3), "r"(b0), "r"(b1));
}

// ---------------- K1: weights prep ----------------
__global__ void k1_prep(const float* __restrict__ anchor,
                        const float* __restrict__ sigma) {
    int k = blockIdx.x;
    int tid = threadIdx.x;
    __shared__ float red[256];
    float ck = 0.f;
    for (int c = tid; c < CC; c += 256) {
        int idx = k*CC + c;
        float s  = 1.f / (1.f + expf(-sigma[idx]));
        float iv = 1.f / (s + 1e-7f);
        float i2 = iv * iv;
        float a  = anchor[idx];
        g_w1t[c*KK + k] = i2;
        g_w2t[c*KK + k] = -2.f * a * i2;
        g_inv[idx] = iv;
        ck += a * a * i2;
    }
    red[tid] = ck; __syncthreads();
    for (int s = 128; s > 0; s >>= 1) {
        if (tid < s) red[tid] += red[tid + s];
        __syncthreads();
    }
    if (tid == 0) g_ck[k] = red[0];
}

// ---------------- K2: distance GEMM (k-paired f32x2, unchanged) ----------------
__global__ void __launch_bounds__(256, 2) k2_dist(const float* __restrict__ x) {
    int bid = blockIdx.x;
    int cs = bid & 15;
    int nt = (bid >> 4) & 3;
    int b  = bid >> 6;
    int c0 = cs * 32, n0 = nt * 256;

    __shared__ float xs[16][264];
    __shared__ float w1s[16][72];
    __shared__ float w2s[16][72];

    int tid = threadIdx.x;
    int kr = tid >> 5;
    int nr = tid & 31;
    int k0 = kr * 8;

    u64 acc[4][8];
#pragma unroll
    for (int i = 0; i < 4; i++)
#pragma unroll
        for (int j = 0; j < 8; j++) acc[i][j] = 0ull;

#pragma unroll
    for (int cc = 0; cc < 32; cc += 16) {
        __syncthreads();
#pragma unroll
        for (int l = 0; l < 4; l++) {
            int idx = tid + l * 256;
            int row = idx >> 6;
            int col = (idx & 63) << 2;
            *(float4*)&xs[row][col] =
                *(const float4*)&x[(b*CC + c0 + cc + row)*HW + n0 + col];
        }
        {
            int rc = tid >> 4;
            int kk = (tid & 15) << 2;
            int g  = (c0 + cc + rc)*KK + kk;
            *(float4*)&w1s[rc][kk] = *(const float4*)&g_w1t[g];
            *(float4*)&w2s[rc][kk] = *(const float4*)&g_w2t[g];
        }
        __syncthreads();
#pragma unroll
        for (int c = 0; c < 16; c++) {
            const float4* xr = (const float4*)&xs[c][0];
            float4 xa = xr[nr];
            float4 xb = xr[nr + 32];
            ulonglong2 w1a = *(const ulonglong2*)&w1s[c][k0];
            ulonglong2 w1b = *(const ulonglong2*)&w1s[c][k0 + 4];
            ulonglong2 w2a = *(const ulonglong2*)&w2s[c][k0];
            ulonglong2 w2b = *(const ulonglong2*)&w2s[c][k0 + 4];
            u64 w1p[4] = {w1a.x, w1a.y, w1b.x, w1b.y};
            u64 w2p[4] = {w2a.x, w2a.y, w2b.x, w2b.y};
            float xn[8] = {xa.x, xa.y, xa.z, xa.w, xb.x, xb.y, xb.z, xb.w};
#pragma unroll
            for (int j = 0; j < 8; j++) {
                u64 xd = dup2(xn[j]);
                u64 xq = mul2(xd, xd);
#pragma unroll
                for (int kp = 0; kp < 4; kp++) {
                    fma2(acc[kp][j], xq, w1p[kp]);
                    fma2(acc[kp][j], xd, w2p[kp]);
                }
            }
        }
    }
#pragma unroll
    for (int kp = 0; kp < 4; kp++) {
        float2 p[8];
#pragma unroll
        for (int j = 0; j < 8; j++) p[j] = unpk(acc[kp][j]);
        int klo = k0 + 2*kp;
        int base = (b*KK + klo)*HW + n0 + nr*4;
        *(float4*)&g_d2p[cs][base]            = make_float4(p[0].x, p[1].x, p[2].x, p[3].x);
        *(float4*)&g_d2p[cs][base + 128]      = make_float4(p[4].x, p[5].x, p[6].x, p[7].x);
        *(float4*)&g_d2p[cs][base + HW]       = make_float4(p[0].y, p[1].y, p[2].y, p[3].y);
        *(float4*)&g_d2p[cs][base + HW + 128] = make_float4(p[4].y, p[5].y, p[6].y, p[7].y);
    }
}

// ---------------- K23: partial reduce + softmax + wsum partials (unchanged) ----------------
__global__ void __launch_bounds__(512, 2) k23(float* __restrict__ soft_out) {
    int b    = blockIdx.x >> 5;
    int tile = blockIdx.x & 31;
    int n0   = tile * 32;
    int tid  = threadIdx.x;
    __shared__ float sm[64][36];

    {
        int k  = tid >> 3;
        int n4 = (tid & 7) << 2;
        int base = (b*KK + k)*HW + n0 + n4;
        float4 s = make_float4(0.f, 0.f, 0.f, 0.f);
#pragma unroll
        for (int p = 0; p < NP2; p++) {
            float4 v = *(const float4*)&g_d2p[p][base];
            s.x += v.x; s.y += v.y; s.z += v.z; s.w += v.w;
        }
        float ck = g_ck[k];
        s.x = -0.5f*(s.x + ck); s.y = -0.5f*(s.y + ck);
        s.z = -0.5f*(s.z + ck); s.w = -0.5f*(s.w + ck);
        *(float4*)&sm[k][n4] = s;
    }
    __syncthreads();

    {
        int n   = tid >> 4;
        int sub = tid & 15;
        float v[4];
        float mx = -3.4e38f;
#pragma unroll
        for (int i = 0; i < 4; i++) {
            v[i] = sm[sub + 16*i][n];
            mx = fmaxf(mx, v[i]);
        }
#pragma unroll
        for (int m = 1; m < 16; m <<= 1)
            mx = fmaxf(mx, __shfl_xor_sync(0xffffffffu, mx, m));
        float s = 0.f;
#pragma unroll
        for (int i = 0; i < 4; i++) { v[i] = __expf(v[i] - mx); s += v[i]; }
#pragma unroll
        for (int m = 1; m < 16; m <<= 1)
            s += __shfl_xor_sync(0xffffffffu, s, m);
        float is = 1.f / s;
#pragma unroll
        for (int i = 0; i < 4; i++)
            sm[sub + 16*i][n] = v[i] * is;
    }
    __syncthreads();

    {
        int k  = tid >> 3;
        int n4 = (tid & 7) << 2;
        *(float4*)&soft_out[(b*KK + k)*HW + n0 + n4] = *(const float4*)&sm[k][n4];
    }
    {
        int k   = tid >> 3;
        int sub = tid & 7;
        float w = 0.f;
#pragma unroll
        for (int j = 0; j < 4; j++) w += sm[k][sub*4 + j];
#pragma unroll
        for (int m = 1; m < 8; m <<= 1)
            w += __shfl_xor_sync(0xffffffffu, w, m);
        if (sub == 0) g_wsp[(b*NWT + tile)*KK + k] = w;
    }
}

// ---------------- K4: aggregation GEMM via tf32 mma.sync ----------------
// D[64k][512c] = sum_n soft[k][n] * x[c][n]. A=soft (row-major k x n),
// B=x (col-major: K=n contiguous, N=c). grid 256 = 4b x 4ct x 16ns, 256 thr.
// Block: full 64k x 128c x 64n-slab (2 chunks of 32n). Warp: 64k x 16c.
// smem stores tf32 with per-8 column perm [0,4,1,5,2,6,3,7] so each frag
// pair (t, t+4) is one LDS.64. Row pad 40 u32 -> conflict-free.
__global__ void __launch_bounds__(256, 2) k4_agg(const float* __restrict__ x,
                                                 const float* __restrict__ soft) {
    int bid = blockIdx.x;
    int ns = bid & 15;
    int ct = (bid >> 4) & 3;
    int b  = bid >> 6;
    int n0 = ns * 64;
    int cb = ct * 128;

    __shared__ u32 As[64][40];    // soft tile [k][32n perm]
    __shared__ u32 Bs[128][40];   // x tile [c][32n perm]

    int tid  = threadIdx.x;
    int w    = tid >> 5;          // warp 0..7 -> c = cb + w*16
    int lane = tid & 31;
    int g    = lane >> 2;         // group 0..7
    int t    = lane & 3;

    float d[4][2][4];             // [m-tile][c8][4]
#pragma unroll
    for (int mt = 0; mt < 4; mt++)
#pragma unroll
        for (int j = 0; j < 2; j++)
#pragma unroll
            for (int r = 0; r < 4; r++) d[mt][j][r] = 0.f;

#pragma unroll
    for (int nc = 0; nc < 64; nc += 32) {
        __syncthreads();
        // fill A: 64k x 32n (512 f4 slots), perm + tf32
#pragma unroll
        for (int l = 0; l < 2; l++) {
            int slot = tid + l * 256;
            int k    = slot >> 3;
            int f4c  = slot & 7;
            float4 v = *(const float4*)&soft[(b*KK + k)*HW + n0 + nc + f4c*4];
            int dbase = ((f4c & ~1) << 2) + (f4c & 1);
            As[k][dbase + 0] = tf32cvt(v.x);
            As[k][dbase + 2] = tf32cvt(v.y);
            As[k][dbase + 4] = tf32cvt(v.z);
            As[k][dbase + 6] = tf32cvt(v.w);
        }
        // fill B: 128c x 32n (1024 f4 slots), perm + tf32
#pragma unroll
        for (int l = 0; l < 4; l++) {
            int slot = tid + l * 256;
            int c    = slot >> 3;
            int f4c  = slot & 7;
            float4 v = *(const float4*)&x[(b*CC + cb + c)*HW + n0 + nc + f4c*4];
            int dbase = ((f4c & ~1) << 2) + (f4c & 1);
            Bs[c][dbase + 0] = tf32cvt(v.x);
            Bs[c][dbase + 2] = tf32cvt(v.y);
            Bs[c][dbase + 4] = tf32cvt(v.z);
            Bs[c][dbase + 6] = tf32cvt(v.w);
        }
        __syncthreads();
#pragma unroll
        for (int ks = 0; ks < 4; ks++) {
            int col = ks*8 + 2*t;
            u32 a0[4], a1[4], a2[4], a3[4];
#pragma unroll
            for (int mt = 0; mt < 4; mt++) {
                uint2 lo = *(const uint2*)&As[mt*16 + g][col];
                uint2 hi = *(const uint2*)&As[mt*16 + g + 8][col];
                a0[mt] = lo.x; a2[mt] = lo.y;
                a1[mt] = hi.x; a3[mt] = hi.y;
            }
#pragma unroll
            for (int j = 0; j < 2; j++) {
                uint2 bb = *(const uint2*)&Bs[w*16 + j*8 + g][col];
#pragma unroll
                for (int mt = 0; mt < 4; mt++)
                    mma_tf32(d[mt][j][0], d[mt][j][1], d[mt][j][2], d[mt][j][3],
                             a0[mt], a1[mt], a2[mt], a3[mt], bb.x, bb.y);
            }
        }
    }
    // epilogue: c0,c1 -> (k=16mt+g, c=cb+w*16+j*8+2t), c2,c3 -> k+8
#pragma unroll
    for (int mt = 0; mt < 4; mt++)
#pragma unroll
        for (int j = 0; j < 2; j++) {
            int c = cb + w*16 + j*8 + 2*t;
            int k = mt*16 + g;
            *(float2*)&g_nump[ns][(b*KK + k)*CC + c]     = make_float2(d[mt][j][0], d[mt][j][1]);
            *(float2*)&g_nump[ns][(b*KK + k + 8)*CC + c] = make_float2(d[mt][j][2], d[mt][j][3]);
        }
}

// ---------------- K5: epilogue + row normalize + folded flat normalize ----------------
__global__ void k5_epilogue(const float* __restrict__ anchor,
                            float* __restrict__ out) {
    int bk = blockIdx.x;
    int k  = bk & 63;
    int b  = bk >> 6;
    int tid = threadIdx.x;
    __shared__ float red[256];

    float ws = 0.f;
#pragma unroll
    for (int p = 0; p < NWT; p++) ws += g_wsp[(b*NWT + p)*KK + k];

    float invden = 1.f / (ws + 1e-7f);
    float node[2];
    float sq = 0.f;
#pragma unroll
    for (int l = 0; l < 2; l++) {
        int c = tid + l * 256;
        int gi = bk * CC + c;
        float num = 0.f;
#pragma unroll
        for (int p = 0; p < NP4; p++) num += g_nump[p][gi];
        num = (num - ws * anchor[k*CC + c]) * g_inv[k*CC + c];
        float nd = num * invden;
        node[l] = nd;
        sq += nd * nd;
    }
    red[tid] = sq; __syncthreads();
    for (int s = 128; s > 0; s >>= 1) {
        if (tid < s) red[tid] += red[tid + s];
        __syncthreads();
    }
    float total = red[0];
    float scale = 0.125f / fmaxf(sqrtf(total), 1e-12f);
#pragma unroll
    for (int l = 0; l < 2; l++)
        out[bk * CC + tid + l * 256] = node[l] * scale;
}

// ---------------- launch ----------------
extern "C" void kernel_launch(void* const* d_in, const int* in_sizes, int n_in,
                              void* d_out, int out_size) {
    const float* x      = (const float*)d_in[0];
    const float* anchor = (const float*)d_in[1];
    const float* sigma  = (const float*)d_in[2];
    float* out = (float*)d_out;
    float* nodes_out = out;                 // B*K*C floats
    float* soft_out  = out + BB*KK*CC;      // B*K*HW floats

    k1_prep    <<<KK, 256>>>(anchor, sigma);
    k2_dist    <<<256, 256>>>(x);
    k23        <<<128, 512>>>(soft_out);
    k4_agg     <<<256, 256>>>(x, soft_out);
    k5_epilogue<<<BB*KK, 256>>>(anchor, nodes_out);
}

// round 8
// speedup vs baseline: 1.7541x; 1.0673x over previous
#include <cuda_runtime.h>
#include <math.h>

#define BB 4
#define CC 512
#define HW 1024
#define KK 64
#define NP2 8    // d2 partial count (C-split)
#define NP4 8    // agg partial count (n-split)
#define NWT 32   // wsum partial tiles

typedef unsigned long long u64;
typedef unsigned int u32;

// ---------------- scratch ----------------
__device__ float g_w1t[CC*KK];            // inv2, c-major [c][k]
__device__ float g_w2t[CC*KK];            // -2*anchor*inv2, c-major [c][k]
__device__ float g_inv[KK*CC];            // inv, k-major
__device__ float g_ck[KK];                // sum_c anchor^2*inv2
__device__ float g_d2p[NP2][BB*KK*HW];    // d2 partials, k-major
__device__ float g_nump[NP4][BB*KK*CC];   // agg partials
__device__ float g_wsp[BB*NWT*KK];        // wsum partials

// ---------------- f32x2 helpers ----------------
__device__ __forceinline__ u64 dup2(float a) {
    u64 r; asm("mov.b64 %0, {%1, %1};" : "=l"(r) : "f"(a)); return r;
}
__device__ __forceinline__ void fma2(u64& d, u64 a, u64 b) {
    asm("fma.rn.f32x2 %0, %1, %2, %0;" : "+l"(d) : "l"(a), "l"(b));
}
__device__ __forceinline__ u64 mul2(u64 a, u64 b) {
    u64 r; asm("mul.rn.f32x2 %0, %1, %2;" : "=l"(r) : "l"(a), "l"(b)); return r;
}
__device__ __forceinline__ float2 unpk(u64 a) {
    float x, y; asm("mov.b64 {%0, %1}, %2;" : "=f"(x), "=f"(y) : "l"(a));
    return make_float2(x, y);
}

// ---------------- tf32 mma helpers ----------------
__device__ __forceinline__ u32 tf32cvt(float f) {
    u32 r; asm("cvt.rna.tf32.f32 %0, %1;" : "=r"(r) : "f"(f)); return r;
}
__device__ __forceinline__ void mma_tf32(float& d0, float& d1, float& d2, float& d3,
                                         u32 a0, u32 a1, u32 a2, u32 a3,
                                         u32 b0, u32 b1) {
    asm("mma.sync.aligned.m16n8k8.row.col.f32.tf32.tf32.f32 "
        "{%0,%1,%2,%3},{%4,%5,%6,%7},{%8,%9},{%0,%1,%2,%3};"
        : "+f"(d0), "+f"(d1), "+f"(d2), "+f"(d3)
        : "r"(a0), "r"(a1), "r"(a2), "r"(a3), "r"(b0), "r"(b1));
}

// ---------------- cp.async helpers ----------------
__device__ __forceinline__ void cpa16(void* s, const void* g) {
    u32 sa = (u32)__cvta_generic_to_shared(s);
    asm volatile("cp.async.cg.shared.global [%0], [%1], 16;" :: "r"(sa), "l"(g));
}
__device__ __forceinline__ void cpcommit() {
    asm volatile("cp.async.commit_group;" ::: "memory");
}
template<int N> __device__ __forceinline__ void cpwait() {
    asm volatile("cp.async.wait_group %0;" :: "n"(N) : "memory");
}

// ---------------- K1: weights prep ----------------
__global__ void k1_prep(const float* __restrict__ anchor,
                        const float* __restrict__ sigma) {
    int k = blockIdx.x;
    int tid = threadIdx.x;
    __shared__ float red[256];
    float ck = 0.f;
    for (int c = tid; c < CC; c += 256) {
        int idx = k*CC + c;
        float s  = 1.f / (1.f + expf(-sigma[idx]));
        float iv = 1.f / (s + 1e-7f);
        float i2 = iv * iv;
        float a  = anchor[idx];
        g_w1t[c*KK + k] = i2;
        g_w2t[c*KK + k] = -2.f * a * i2;
        g_inv[idx] = iv;
        ck += a * a * i2;
    }
    red[tid] = ck; __syncthreads();
    for (int s = 128; s > 0; s >>= 1) {
        if (tid < s) red[tid] += red[tid + s];
        __syncthreads();
    }
    if (tid == 0) g_ck[k] = red[0];
}

// ---------------- K2: distance GEMM, cp.async double-buffer ----------------
// grid 256 = 4b x 8nt x 8cs, 256 thr. Block: 64k x 128n x 64c (4 chunks of 16c).
// Thread: 8k x 4n, f32x2 along k pairs. Static smem 2 x 4288 floats = 34.3KB.
#define S2STRIDE 4288   // 16*132 (x) + 16*68 (w1) + 16*68 (w2)
__global__ void __launch_bounds__(256, 2) k2_dist(const float* __restrict__ x) {
    __shared__ float sm2[2][S2STRIDE];
    int bid = blockIdx.x;
    int cs = bid & 7;
    int nt = (bid >> 3) & 7;
    int b  = bid >> 6;
    int c0 = cs * 64, n0 = nt * 128;

    int tid = threadIdx.x;
    int kr = tid >> 5;     // warp-uniform -> k0 = kr*8
    int nr = tid & 31;     // n = n0 + nr*4 + {0..3}
    int k0 = kr * 8;

    u64 acc[4][4];         // [k-pair][n]
#pragma unroll
    for (int i = 0; i < 4; i++)
#pragma unroll
        for (int j = 0; j < 4; j++) acc[i][j] = 0ull;

    auto fill = [&](int s, int cc) {
        float* xs = sm2[s];
        float* w1 = xs + 16*132;
        float* w2 = w1 + 16*68;
#pragma unroll
        for (int l = 0; l < 2; l++) {
            int slot = tid + l * 256;            // 512 f4 slots: 16c x 32 n-f4
            int row = slot >> 5;
            int col = (slot & 31) << 2;
            cpa16(&xs[row*132 + col], &x[(b*CC + c0 + cc + row)*HW + n0 + col]);
        }
        {
            int rc = tid >> 4;                   // 256 f4 slots each
            int kk = (tid & 15) << 2;
            cpa16(&w1[rc*68 + kk], &g_w1t[(c0 + cc + rc)*KK + kk]);
            cpa16(&w2[rc*68 + kk], &g_w2t[(c0 + cc + rc)*KK + kk]);
        }
        cpcommit();
    };

    auto comp = [&](int s) {
        float* xs = sm2[s];
        float* w1 = xs + 16*132;
        float* w2 = w1 + 16*68;
#pragma unroll
        for (int c = 0; c < 16; c++) {
            float4 xa = *(const float4*)&xs[c*132 + nr*4];
            ulonglong2 w1a = *(const ulonglong2*)&w1[c*68 + k0];
            ulonglong2 w1b = *(const ulonglong2*)&w1[c*68 + k0 + 4];
            ulonglong2 w2a = *(const ulonglong2*)&w2[c*68 + k0];
            ulonglong2 w2b = *(const ulonglong2*)&w2[c*68 + k0 + 4];
            u64 w1p[4] = {w1a.x, w1a.y, w1b.x, w1b.y};
            u64 w2p[4] = {w2a.x, w2a.y, w2b.x, w2b.y};
            float xn[4] = {xa.x, xa.y, xa.z, xa.w};
#pragma unroll
            for (int j = 0; j < 4; j++) {
                u64 xd = dup2(xn[j]);
                u64 xq = mul2(xd, xd);
#pragma unroll
                for (int kp = 0; kp < 4; kp++) {
                    fma2(acc[kp][j], xq, w1p[kp]);
                    fma2(acc[kp][j], xd, w2p[kp]);
                }
            }
        }
    };

    // 4 chunks of 16c, double-buffered
    fill(0, 0);
    fill(1, 16); cpwait<1>(); __syncthreads(); comp(0); __syncthreads();
    fill(0, 32); cpwait<1>(); __syncthreads(); comp(1); __syncthreads();
    fill(1, 48); cpwait<1>(); __syncthreads(); comp(0); __syncthreads();
                 cpwait<0>(); __syncthreads(); comp(1);

    // store 8k x 4n, k-major coalesced
#pragma unroll
    for (int kp = 0; kp < 4; kp++) {
        float2 p0 = unpk(acc[kp][0]), p1 = unpk(acc[kp][1]);
        float2 p2 = unpk(acc[kp][2]), p3 = unpk(acc[kp][3]);
        int klo = k0 + 2*kp;
        int base = (b*KK + klo)*HW + n0 + nr*4;
        *(float4*)&g_d2p[cs][base]      = make_float4(p0.x, p1.x, p2.x, p3.x);
        *(float4*)&g_d2p[cs][base + HW] = make_float4(p0.y, p1.y, p2.y, p3.y);
    }
}

// ---------------- K23: partial reduce + softmax + wsum partials ----------------
// grid 128 = 4b x 32 tiles(32n), 512 thr.
__global__ void __launch_bounds__(512, 2) k23(float* __restrict__ soft_out) {
    int b    = blockIdx.x >> 5;
    int tile = blockIdx.x & 31;
    int n0   = tile * 32;
    int tid  = threadIdx.x;
    __shared__ float sm[64][36];

    {
        int k  = tid >> 3;
        int n4 = (tid & 7) << 2;
        int base = (b*KK + k)*HW + n0 + n4;
        float4 s = make_float4(0.f, 0.f, 0.f, 0.f);
#pragma unroll
        for (int p = 0; p < NP2; p++) {
            float4 v = *(const float4*)&g_d2p[p][base];
            s.x += v.x; s.y += v.y; s.z += v.z; s.w += v.w;
        }
        float ck = g_ck[k];
        s.x = -0.5f*(s.x + ck); s.y = -0.5f*(s.y + ck);
        s.z = -0.5f*(s.z + ck); s.w = -0.5f*(s.w + ck);
        *(float4*)&sm[k][n4] = s;
    }
    __syncthreads();

    {
        int n   = tid >> 4;
        int sub = tid & 15;
        float v[4];
        float mx = -3.4e38f;
#pragma unroll
        for (int i = 0; i < 4; i++) {
            v[i] = sm[sub + 16*i][n];
            mx = fmaxf(mx, v[i]);
        }
#pragma unroll
        for (int m = 1; m < 16; m <<= 1)
            mx = fmaxf(mx, __shfl_xor_sync(0xffffffffu, mx, m));
        float s = 0.f;
#pragma unroll
        for (int i = 0; i < 4; i++) { v[i] = __expf(v[i] - mx); s += v[i]; }
#pragma unroll
        for (int m = 1; m < 16; m <<= 1)
            s += __shfl_xor_sync(0xffffffffu, s, m);
        float is = 1.f / s;
#pragma unroll
        for (int i = 0; i < 4; i++)
            sm[sub + 16*i][n] = v[i] * is;
    }
    __syncthreads();

    {
        int k  = tid >> 3;
        int n4 = (tid & 7) << 2;
        *(float4*)&soft_out[(b*KK + k)*HW + n0 + n4] = *(const float4*)&sm[k][n4];
    }
    {
        int k   = tid >> 3;
        int sub = tid & 7;
        float w = 0.f;
#pragma unroll
        for (int j = 0; j < 4; j++) w += sm[k][sub*4 + j];
#pragma unroll
        for (int m = 1; m < 8; m <<= 1)
            w += __shfl_xor_sync(0xffffffffu, w, m);
        if (sub == 0) g_wsp[(b*NWT + tile)*KK + k] = w;
    }
}

// ---------------- K4: aggregation GEMM, tf32 mma + cp.async 3-stage ----------------
// grid 128 = 4b x 4ct x 8ns, 256 thr. Block: 64k x 128c x 128n (8 chunks of 16n).
// Warp: 64k x 16c. Static smem 3 x 3840 floats = 46.1KB (fp32 raw, cvt after LDS).
// Pitch 20 words: frag banks (20g + t) mod 32 all distinct -> conflict-free.
#define S4STRIDE 3840   // 64*20 + 128*20
__global__ void __launch_bounds__(256, 2) k4_agg(const float* __restrict__ x,
                                                 const float* __restrict__ soft) {
    __shared__ float sm4[3][S4STRIDE];
    int bid = blockIdx.x;
    int ns = bid & 7;
    int ct = (bid >> 3) & 3;
    int b  = bid >> 5;
    int n0 = ns * 128;
    int cb = ct * 128;

    int tid  = threadIdx.x;
    int w    = tid >> 5;          // warp -> c = cb + w*16
    int lane = tid & 31;
    int g    = lane >> 2;
    int t    = lane & 3;

    float d[4][2][4];
#pragma unroll
    for (int mt = 0; mt < 4; mt++)
#pragma unroll
        for (int j = 0; j < 2; j++)
#pragma unroll
            for (int r = 0; r < 4; r++) d[mt][j][r] = 0.f;

    auto fill = [&](int s, int chunk) {
        float* As = sm4[s];
        float* Bs = As + 64*20;
        int nc = chunk * 16;
        {
            int k  = tid >> 2;               // 256 f4: 64k x 4 n-f4
            int f4 = (tid & 3) << 2;
            cpa16(&As[k*20 + f4], &soft[(b*KK + k)*HW + n0 + nc + f4]);
        }
#pragma unroll
        for (int l = 0; l < 2; l++) {
            int slot = tid + l * 256;        // 512 f4: 128c x 4 n-f4
            int c  = slot >> 2;
            int f4 = (slot & 3) << 2;
            cpa16(&Bs[c*20 + f4], &x[(b*CC + cb + c)*HW + n0 + nc + f4]);
        }
        cpcommit();
    };

    auto comp = [&](int s) {
        float* As = sm4[s];
        float* Bs = As + 64*20;
#pragma unroll
        for (int ks = 0; ks < 2; ks++) {
            int col = ks*8 + t;
            u32 a0[4], a1[4], a2[4], a3[4];
#pragma unroll
            for (int mt = 0; mt < 4; mt++) {
                a0[mt] = tf32cvt(As[(mt*16 + g)*20     + col]);
                a1[mt] = tf32cvt(As[(mt*16 + g + 8)*20 + col]);
                a2[mt] = tf32cvt(As[(mt*16 + g)*20     + col + 4]);
                a3[mt] = tf32cvt(As[(mt*16 + g + 8)*20 + col + 4]);
            }
#pragma unroll
            for (int j = 0; j < 2; j++) {
                u32 b0 = tf32cvt(Bs[(w*16 + j*8 + g)*20 + col]);
                u32 b1 = tf32cvt(Bs[(w*16 + j*8 + g)*20 + col + 4]);
#pragma unroll
                for (int mt = 0; mt < 4; mt++)
                    mma_tf32(d[mt][j][0], d[mt][j][1], d[mt][j][2], d[mt][j][3],
                             a0[mt], a1[mt], a2[mt], a3[mt], b0, b1);
            }
        }
    };

    // 8 chunks of 16n, 3-stage ring, depth-2 prefetch
    fill(0, 0); fill(1, 1);
    fill(2, 2); cpwait<2>(); __syncthreads(); comp(0); __syncthreads();
    fill(0, 3); cpwait<2>(); __syncthreads(); comp(1); __syncthreads();
    fill(1, 4); cpwait<2>(); __syncthreads(); comp(2); __syncthreads();
    fill(2, 5); cpwait<2>(); __syncthreads(); comp(0); __syncthreads();
    fill(0, 6); cpwait<2>(); __syncthreads(); comp(1); __syncthreads();
    fill(1, 7); cpwait<2>(); __syncthreads(); comp(2); __syncthreads();
                cpwait<1>(); __syncthreads(); comp(0); __syncthreads();
                cpwait<0>(); __syncthreads(); comp(1);

#pragma unroll
    for (int mt = 0; mt < 4; mt++)
#pragma unroll
        for (int j = 0; j < 2; j++) {
            int c = cb + w*16 + j*8 + 2*t;
            int k = mt*16 + g;
            *(float2*)&g_nump[ns][(b*KK + k)*CC + c]     = make_float2(d[mt][j][0], d[mt][j][1]);
            *(float2*)&g_nump[ns][(b*KK + k + 8)*CC + c] = make_float2(d[mt][j][2], d[mt][j][3]);
        }
}

// ---------------- K5: epilogue + row normalize + folded flat normalize ----------------
__global__ void k5_epilogue(const float* __restrict__ anchor,
                            float* __restrict__ out) {
    int bk = blockIdx.x;
    int k  = bk & 63;
    int b  = bk >> 6;
    int tid = threadIdx.x;
    __shared__ float red[256];

    float ws = 0.f;
#pragma unroll
    for (int p = 0; p < NWT; p++) ws += g_wsp[(b*NWT + p)*KK + k];

    float invden = 1.f / (ws + 1e-7f);
    float node[2];
    float sq = 0.f;
#pragma unroll
    for (int l = 0; l < 2; l++) {
        int c = tid + l * 256;
        int gi = bk * CC + c;
        float num = 0.f;
#pragma unroll
        for (int p = 0; p < NP4; p++) num += g_nump[p][gi];
        num = (num - ws * anchor[k*CC + c]) * g_inv[k*CC + c];
        float nd = num * invden;
        node[l] = nd;
        sq += nd * nd;
    }
    red[tid] = sq; __syncthreads();
    for (int s = 128; s > 0; s >>= 1) {
        if (tid < s) red[tid] += red[tid + s];
        __syncthreads();
    }
    float total = red[0];
    float scale = 0.125f / fmaxf(sqrtf(total), 1e-12f);
#pragma unroll
    for (int l = 0; l < 2; l++)
        out[bk * CC + tid + l * 256] = node[l] * scale;
}

// ---------------- launch ----------------
extern "C" void kernel_launch(void* const* d_in, const int* in_sizes, int n_in,
                              void* d_out, int out_size) {
    const float* x      = (const float*)d_in[0];
    const float* anchor = (const float*)d_in[1];
    const float* sigma  = (const float*)d_in[2];
    float* out = (float*)d_out;
    float* nodes_out = out;                 // B*K*C floats
    float* soft_out  = out + BB*KK*CC;      // B*K*HW floats

    k1_prep    <<<KK, 256>>>(anchor, sigma);
    k2_dist    <<<256, 256>>>(x);
    k23        <<<128, 512>>>(soft_out);
    k4_agg     <<<128, 256>>>(x, soft_out);
    k5_epilogue<<<BB*KK, 256>>>(anchor, nodes_out);
}